// round 3
// baseline (speedup 1.0000x reference)
#include <cuda_runtime.h>
#include <cuda_bf16.h>
#include <cstdint>

#define IN_DIM 128
#define OUT_DIM 64
#define MAXN 50000
#define MAXE 1600000
#define SLOPE 0.1f
#define EPS 1e-12f

// Scratch (static device globals — allocation is forbidden)
__device__ __align__(256) float  g_new[MAXN * OUT_DIM];  // transformed features [N,64]
__device__ float  g_ssrc[MAXN];          // new[n] . a_src
__device__ float  g_sdst[MAXN];          // new[n] . a_dst
__device__ int    g_cnt[MAXN];           // out-degree histogram
__device__ int    g_base[MAXN + 1];      // CSR offsets (mutated by k_place into end[])
__device__ __align__(16) float2 g_edge[MAXE];  // src-sorted {ev, dst_bits}

// ---------------------------------------------------------------------------
// Kernel 1: new = x @ W^T + b ; per-node scores ; zero histogram
// One thread per node, 64 fp32 accumulators, W broadcast from smem.
// ---------------------------------------------------------------------------
__global__ __launch_bounds__(256) void k_transform(
    const float* __restrict__ x, const float* __restrict__ W,
    const float* __restrict__ b, const float* __restrict__ a, int nN)
{
    __shared__ __align__(16) float sW[OUT_DIM * IN_DIM];
    __shared__ float sb[OUT_DIM], sas[OUT_DIM], sad[OUT_DIM];
    for (int i = threadIdx.x; i < OUT_DIM * IN_DIM; i += blockDim.x) sW[i] = W[i];
    if (threadIdx.x < OUT_DIM) {
        sb[threadIdx.x]  = b[threadIdx.x];
        sas[threadIdx.x] = a[threadIdx.x];
        sad[threadIdx.x] = a[OUT_DIM + threadIdx.x];
    }
    __syncthreads();

    int n = blockIdx.x * blockDim.x + threadIdx.x;
    if (n >= nN) return;

    g_cnt[n] = 0;   // re-zero histogram every launch (graph-replay safe)

    const float4* __restrict__ x4 = (const float4*)(x + (size_t)n * IN_DIM);
    const float4* __restrict__ W4 = (const float4*)sW;

    float acc[OUT_DIM];
#pragma unroll
    for (int d = 0; d < OUT_DIM; d++) acc[d] = 0.f;

    for (int kk = 0; kk < IN_DIM / 4; kk++) {
        float4 xv = x4[kk];
#pragma unroll
        for (int d = 0; d < OUT_DIM; d++) {
            float4 wv = W4[d * (IN_DIM / 4) + kk];   // warp-broadcast from smem
            acc[d] += xv.x * wv.x + xv.y * wv.y + xv.z * wv.z + xv.w * wv.w;
        }
    }

    float ss = 0.f, sd = 0.f;
    float4* newv4 = (float4*)(g_new + (size_t)n * OUT_DIM);
#pragma unroll
    for (int j = 0; j < OUT_DIM / 4; j++) {
        float v0 = acc[4*j+0] + sb[4*j+0];
        float v1 = acc[4*j+1] + sb[4*j+1];
        float v2 = acc[4*j+2] + sb[4*j+2];
        float v3 = acc[4*j+3] + sb[4*j+3];
        newv4[j] = make_float4(v0, v1, v2, v3);
        ss += v0*sas[4*j+0] + v1*sas[4*j+1] + v2*sas[4*j+2] + v3*sas[4*j+3];
        sd += v0*sad[4*j+0] + v1*sad[4*j+1] + v2*sad[4*j+2] + v3*sad[4*j+3];
    }
    g_ssrc[n] = ss;
    g_sdst[n] = sd;
}

// ---------------------------------------------------------------------------
// Kernel 2: histogram of src  (edge_index is int32: JAX x64 is disabled)
// ---------------------------------------------------------------------------
__global__ __launch_bounds__(256) void k_hist(
    const int* __restrict__ eidx, int nE, int nN)
{
    int e = blockIdx.x * blockDim.x + threadIdx.x;
    if (e >= nE) return;
    int s = eidx[e];
    s = min(max(s, 0), nN - 1);          // safety clamp
    atomicAdd(&g_cnt[s], 1);
}

// ---------------------------------------------------------------------------
// Kernel 3: exclusive scan of g_cnt -> g_base  (single block, warp-shuffle
// scan, 1024-element chunks with running carry)
// ---------------------------------------------------------------------------
__global__ __launch_bounds__(1024) void k_scan(int nN)
{
    __shared__ int swarp[32];
    __shared__ int scarry;
    int lane = threadIdx.x & 31;
    int wid  = threadIdx.x >> 5;
    if (threadIdx.x == 0) scarry = 0;
    __syncthreads();

    for (int baseI = 0; baseI < nN; baseI += 1024) {
        int i = baseI + threadIdx.x;
        int v = (i < nN) ? g_cnt[i] : 0;

        int inc = v;
#pragma unroll
        for (int off = 1; off < 32; off <<= 1) {
            int t = __shfl_up_sync(0xFFFFFFFF, inc, off);
            if (lane >= off) inc += t;
        }
        if (lane == 31) swarp[wid] = inc;
        __syncthreads();

        if (wid == 0) {
            int wv = swarp[lane];
            int winc = wv;
#pragma unroll
            for (int off = 1; off < 32; off <<= 1) {
                int t = __shfl_up_sync(0xFFFFFFFF, winc, off);
                if (lane >= off) winc += t;
            }
            swarp[lane] = winc - wv;   // exclusive warp offsets
        }
        __syncthreads();

        int excl = scarry + swarp[wid] + inc - v;
        if (i < nN) g_base[i] = excl;

        __syncthreads();
        if (threadIdx.x == 1023) scarry = excl + v;
        __syncthreads();
    }
    if (threadIdx.x == 0) g_base[nN] = scarry;
}

// ---------------------------------------------------------------------------
// Kernel 4: per-edge score -> ev ; place {ev,dst} into CSR slot.
// atomicAdd on g_base doubles as the cursor; afterwards g_base[n] == end[n].
// ---------------------------------------------------------------------------
__global__ __launch_bounds__(256) void k_place(
    const int* __restrict__ eidx, int nE, int nN)
{
    int e = blockIdx.x * blockDim.x + threadIdx.x;
    if (e >= nE) return;
    int s = eidx[e];
    int d = eidx[(size_t)nE + e];
    s = min(max(s, 0), nN - 1);          // safety clamp
    d = min(max(d, 0), nN - 1);
    float sc = g_ssrc[s] + g_sdst[d];
    sc = sc > 0.f ? sc : SLOPE * sc;
    float ev = expf(sc);
    int pos = atomicAdd(&g_base[s], 1);
    g_edge[pos] = make_float2(ev, __int_as_float(d));
}

// ---------------------------------------------------------------------------
// Kernel 5: gather-aggregate + normalize. 16 lanes per node; lane c owns
// float4 chunk c of the 64-dim row. No atomics; one coalesced write.
// After k_place: beg[n] = (n ? g_base[n-1] : 0), end[n] = g_base[n].
// ---------------------------------------------------------------------------
__global__ __launch_bounds__(256) void k_aggregate(
    float* __restrict__ out, int nN)
{
    int n = blockIdx.x * 16 + (threadIdx.x >> 4);
    int c = threadIdx.x & 15;
    if (n >= nN) return;

    int beg = (n == 0) ? 0 : g_base[n - 1];
    int end = g_base[n];

    float4 acc = make_float4(0.f, 0.f, 0.f, 0.f);
    float rs = 0.f;
    for (int i = beg; i < end; i++) {
        float2 p = g_edge[i];             // broadcast across the 16 lanes
        float ev = p.x;
        int  dst = __float_as_int(p.y);
        float4 v = *(const float4*)(g_new + (size_t)dst * OUT_DIM + c * 4);
        acc.x += ev * v.x;
        acc.y += ev * v.y;
        acc.z += ev * v.z;
        acc.w += ev * v.w;
        rs += ev;
    }
    float inv = 1.f / (rs + EPS);
    acc.x *= inv; acc.y *= inv; acc.z *= inv; acc.w *= inv;
    *(float4*)(out + (size_t)n * OUT_DIM + c * 4) = acc;
}

// ---------------------------------------------------------------------------
extern "C" void kernel_launch(void* const* d_in, const int* in_sizes, int n_in,
                              void* d_out, int out_size)
{
    const float* x    = (const float*)d_in[0];
    const int*   eidx = (const int*)d_in[1];    // int32! (JAX x64 disabled)
    const float* W    = (const float*)d_in[2];
    const float* b    = (const float*)d_in[3];
    const float* a    = (const float*)d_in[4];
    float* out = (float*)d_out;

    int nN = in_sizes[0] / IN_DIM;   // 50000
    int nE = in_sizes[1] / 2;        // 1600000

    k_transform<<<(nN + 255) / 256, 256>>>(x, W, b, a, nN);
    k_hist<<<(nE + 255) / 256, 256>>>(eidx, nE, nN);
    k_scan<<<1, 1024>>>(nN);
    k_place<<<(nE + 255) / 256, 256>>>(eidx, nE, nN);
    k_aggregate<<<(nN + 15) / 16, 256>>>(out, nN);
}

// round 4
// speedup vs baseline: 1.4500x; 1.4500x over previous
#include <cuda_runtime.h>
#include <cuda_fp16.h>
#include <cstdint>

#define IN_DIM 128
#define OUT_DIM 64
#define MAXN 50000
#define MAXE 1600000
#define SLOPE 0.1f
#define EPS 1e-12f
#define SCAN_BLK 1024
#define MAX_SCAN_BLOCKS 64

// Scratch (static device globals — allocation is forbidden). All zero-init at load.
__device__ __align__(256) __half g_newh[MAXN * OUT_DIM]; // transformed features, fp16
__device__ float  g_ssrc[MAXN];          // new[n] . a_src
__device__ float  g_sdst[MAXN];          // new[n] . a_dst
__device__ int    g_cnt[MAXN];           // out-degree histogram (zeroed by k_aggregate)
__device__ int    g_base[MAXN];          // CSR offsets (mutated by k_place into end[])
__device__ int    g_csr[MAXE];           // src-sorted dst indices
__device__ int    g_bsum[MAX_SCAN_BLOCKS];   // scan block aggregates
__device__ int    g_flag[MAX_SCAN_BLOCKS];   // scan publish flags (zeroed by k_fused)

// ---------------------------------------------------------------------------
// Kernel 1 (fused): blocks [0, nbT): transform new = x@W^T+b -> fp16, scores.
//                   blocks [nbT, ...): histogram of src (g_cnt pre-zeroed by
//                   previous launch's k_aggregate / static init).
//                   Block 0 also zeroes the scan flags.
// ---------------------------------------------------------------------------
__global__ __launch_bounds__(256) void k_fused(
    const float* __restrict__ x, const float* __restrict__ W,
    const float* __restrict__ b, const float* __restrict__ a,
    const int* __restrict__ eidx, int nN, int nE, int nbT)
{
    if ((int)blockIdx.x >= nbT) {
        // ---- histogram part ----
        int tidg   = (blockIdx.x - nbT) * blockDim.x + threadIdx.x;
        int stride = (gridDim.x - nbT) * blockDim.x;
        for (int e = tidg; e < nE; e += stride) {
            int s = eidx[e];
            s = min(max(s, 0), nN - 1);
            atomicAdd(&g_cnt[s], 1);
        }
        return;
    }

    // ---- transform part ----
    if (blockIdx.x == 0 && threadIdx.x < MAX_SCAN_BLOCKS) g_flag[threadIdx.x] = 0;

    __shared__ __align__(16) float sW[OUT_DIM * IN_DIM];
    __shared__ float sb[OUT_DIM], sas[OUT_DIM], sad[OUT_DIM];
    for (int i = threadIdx.x; i < OUT_DIM * IN_DIM; i += blockDim.x) sW[i] = W[i];
    if (threadIdx.x < OUT_DIM) {
        sb[threadIdx.x]  = b[threadIdx.x];
        sas[threadIdx.x] = a[threadIdx.x];
        sad[threadIdx.x] = a[OUT_DIM + threadIdx.x];
    }
    __syncthreads();

    int n = blockIdx.x * blockDim.x + threadIdx.x;
    if (n >= nN) return;

    const float4* __restrict__ x4 = (const float4*)(x + (size_t)n * IN_DIM);
    const float4* __restrict__ W4 = (const float4*)sW;

    float acc[OUT_DIM];
#pragma unroll
    for (int d = 0; d < OUT_DIM; d++) acc[d] = 0.f;

    for (int kk = 0; kk < IN_DIM / 4; kk++) {
        float4 xv = x4[kk];
#pragma unroll
        for (int d = 0; d < OUT_DIM; d++) {
            float4 wv = W4[d * (IN_DIM / 4) + kk];   // warp-broadcast from smem
            acc[d] += xv.x * wv.x + xv.y * wv.y + xv.z * wv.z + xv.w * wv.w;
        }
    }

    float ss = 0.f, sd = 0.f;
    uint2* newh = (uint2*)(g_newh + ((size_t)n << 6));   // 4 halves per uint2
#pragma unroll
    for (int j = 0; j < OUT_DIM / 4; j++) {
        float v0 = acc[4*j+0] + sb[4*j+0];
        float v1 = acc[4*j+1] + sb[4*j+1];
        float v2 = acc[4*j+2] + sb[4*j+2];
        float v3 = acc[4*j+3] + sb[4*j+3];
        __half2 h0 = __float22half2_rn(make_float2(v0, v1));
        __half2 h1 = __float22half2_rn(make_float2(v2, v3));
        uint2 hv;
        hv.x = *(unsigned int*)&h0;
        hv.y = *(unsigned int*)&h1;
        newh[j] = hv;
        ss += v0*sas[4*j+0] + v1*sas[4*j+1] + v2*sas[4*j+2] + v3*sas[4*j+3];
        sd += v0*sad[4*j+0] + v1*sad[4*j+1] + v2*sad[4*j+2] + v3*sad[4*j+3];
    }
    g_ssrc[n] = ss;
    g_sdst[n] = sd;
}

// ---------------------------------------------------------------------------
// Kernel 2: exclusive scan of g_cnt -> g_base, decoupled lookback.
// 49 blocks, all concurrently resident (49 << 148 SMs) so spin cannot deadlock.
// ---------------------------------------------------------------------------
__global__ __launch_bounds__(SCAN_BLK) void k_scan(int nN)
{
    __shared__ int swarp[32];
    __shared__ int s_total;
    __shared__ int s_boff;
    int tid  = threadIdx.x;
    int lane = tid & 31;
    int wid  = tid >> 5;
    int bid  = blockIdx.x;
    int i    = bid * SCAN_BLK + tid;

    int v = (i < nN) ? g_cnt[i] : 0;

    // block-wide inclusive scan
    int inc = v;
#pragma unroll
    for (int off = 1; off < 32; off <<= 1) {
        int t = __shfl_up_sync(0xFFFFFFFF, inc, off);
        if (lane >= off) inc += t;
    }
    if (lane == 31) swarp[wid] = inc;
    __syncthreads();
    if (wid == 0) {
        int wv = swarp[lane];
        int winc = wv;
#pragma unroll
        for (int off = 1; off < 32; off <<= 1) {
            int t = __shfl_up_sync(0xFFFFFFFF, winc, off);
            if (lane >= off) winc += t;
        }
        swarp[lane] = winc - wv;   // exclusive warp offsets
    }
    __syncthreads();
    int incl = swarp[wid] + inc;          // block-wide inclusive
    if (tid == SCAN_BLK - 1) s_total = incl;
    __syncthreads();

    // publish block aggregate
    if (tid == 0) {
        g_bsum[bid] = s_total;
        __threadfence();
        *(volatile int*)&g_flag[bid] = 1;
    }

    // lookback: warp 0 sums all predecessor aggregates
    if (wid == 0) {
        int off = 0;
        for (int base = 0; base < bid; base += 32) {
            int j = base + lane;
            int vj = 0;
            if (j < bid) {
                while (*(volatile int*)&g_flag[j] == 0) {}
                __threadfence();
                vj = *(volatile int*)&g_bsum[j];
            }
#pragma unroll
            for (int o = 16; o > 0; o >>= 1)
                vj += __shfl_down_sync(0xFFFFFFFF, vj, o);
            off += __shfl_sync(0xFFFFFFFF, vj, 0);
        }
        if (lane == 0) s_boff = off;
    }
    __syncthreads();

    if (i < nN) g_base[i] = s_boff + incl - v;   // exclusive prefix
}

// ---------------------------------------------------------------------------
// Kernel 3: place dst into CSR slot. atomicAdd on g_base doubles as cursor;
// afterwards g_base[n] == end[n].
// ---------------------------------------------------------------------------
__global__ __launch_bounds__(256) void k_place(
    const int* __restrict__ eidx, int nE, int nN)
{
    int e = blockIdx.x * blockDim.x + threadIdx.x;
    if (e >= nE) return;
    int s = eidx[e];
    int d = eidx[(size_t)nE + e];
    s = min(max(s, 0), nN - 1);
    d = min(max(d, 0), nN - 1);
    int pos = atomicAdd(&g_base[s], 1);
    g_csr[pos] = d;
}

// ---------------------------------------------------------------------------
// Kernel 4: gather-aggregate + normalize. 16 lanes per node, lane c owns
// halves [4c,4c+4) of the 64-dim row. src score is uniform per segment, so
// exp(leakyrelu(.)) is recomputed here (MUFU is free vs the L2 traffic saved).
// Also re-zeroes g_cnt for the next launch.
// ---------------------------------------------------------------------------
__global__ __launch_bounds__(256) void k_aggregate(
    float* __restrict__ out, int nN)
{
    int n = blockIdx.x * 16 + (threadIdx.x >> 4);
    int c = threadIdx.x & 15;
    if (n >= nN) return;

    int beg = (n == 0) ? 0 : g_base[n - 1];
    int end = g_base[n];
    float ssn = g_ssrc[n];

    float4 acc = make_float4(0.f, 0.f, 0.f, 0.f);
    float rs = 0.f;
    for (int i = beg; i < end; i++) {
        int dst = g_csr[i];                       // broadcast across 16 lanes
        float sc = ssn + g_sdst[dst];
        sc = sc > 0.f ? sc : SLOPE * sc;
        float ev = __expf(sc);
        uint2 hv = *(const uint2*)(g_newh + ((size_t)dst << 6) + c * 4);
        float2 f0 = __half22float2(*(__half2*)&hv.x);
        float2 f1 = __half22float2(*(__half2*)&hv.y);
        acc.x += ev * f0.x;
        acc.y += ev * f0.y;
        acc.z += ev * f1.x;
        acc.w += ev * f1.y;
        rs += ev;
    }
    float inv = 1.f / (rs + EPS);
    acc.x *= inv; acc.y *= inv; acc.z *= inv; acc.w *= inv;
    *(float4*)(out + ((size_t)n << 6) + c * 4) = acc;

    if (c == 0) g_cnt[n] = 0;   // clean for next launch (graph replay)
}

// ---------------------------------------------------------------------------
extern "C" void kernel_launch(void* const* d_in, const int* in_sizes, int n_in,
                              void* d_out, int out_size)
{
    const float* x    = (const float*)d_in[0];
    const int*   eidx = (const int*)d_in[1];    // int32 (JAX x64 disabled)
    const float* W    = (const float*)d_in[2];
    const float* b    = (const float*)d_in[3];
    const float* a    = (const float*)d_in[4];
    float* out = (float*)d_out;

    int nN = in_sizes[0] / IN_DIM;   // 50000
    int nE = in_sizes[1] / 2;        // 1600000

    int nbT = (nN + 255) / 256;                  // transform blocks
    int nbH = 1024;                              // histogram blocks (grid-stride)
    k_fused<<<nbT + nbH, 256>>>(x, W, b, a, eidx, nN, nE, nbT);

    int nbS = (nN + SCAN_BLK - 1) / SCAN_BLK;    // 49 <= MAX_SCAN_BLOCKS
    k_scan<<<nbS, SCAN_BLK>>>(nN);

    k_place<<<(nE + 255) / 256, 256>>>(eidx, nE, nN);
    k_aggregate<<<(nN + 15) / 16, 256>>>(out, nN);
}